// round 15
// baseline (speedup 1.0000x reference)
#include <cuda_runtime.h>
#include <cuda_fp16.h>
#include <cstdint>

#define DIN   4096
#define DOUT  4096
#define MTOT  8192
#define BM    128
#define BN    128
#define BK    32
#define NKT   (DIN / BK)      // 128
#define STAGES 5
#define ASTAGE 10240          // 128 rows * 5 chunks * 16B (padded)
#define STAGEB 20480          // A + B per stage
#define NTILES 2048           // (8192/128)*(4096/128)
#define GRID   296            // 148 SMs * 2 CTAs

// Packed fp16 operand tiles. Tile (mb,kt) / (nb,kt) = 4096 halves contiguous,
// chunk c (16B, 8 halves) = row (c>>2), kchunk (c&3). A: [M][K]; B: [N][K] (W transposed).
__device__ __half g_A[(size_t)MTOT * DIN];
__device__ __half g_B[(size_t)DOUT * DIN];

__device__ __forceinline__ uint32_t smem_u32(const void* p) {
    uint32_t a;
    asm("{ .reg .u64 t; cvta.to.shared.u64 t, %1; cvt.u32.u64 %0, t; }" : "=r"(a) : "l"(p));
    return a;
}
__device__ __forceinline__ void cp16(uint32_t dst, const void* src) {
    asm volatile("cp.async.cg.shared.global [%0], [%1], 16;\n" :: "r"(dst), "l"(src));
}

// ---------- fused prep: blocks [0,8192) pack x, [8192,12288) fuse+transpose W ----------
__global__ void __launch_bounds__(256) pack_all(const float* __restrict__ x,
                                                const float* __restrict__ base,
                                                const int* __restrict__ mask,
                                                const float* __restrict__ coeff) {
    __shared__ uint32_t sw32[128 * 17];              // used only by W blocks
    int bx = blockIdx.x;
    int t = threadIdx.x;

    if (bx < 8192) {
        // ---- pack x ----
        int mb = bx >> 7, kt = bx & 127;
        __half* tile = g_A + ((size_t)(mb * NKT + kt) << 12);
        #pragma unroll
        for (int it = 0; it < 2; it++) {
            int cid = it * 256 + t;                  // 512 chunks of 8 halves
            int row = cid >> 2, kc = cid & 3;
            const float4* src = (const float4*)(x + (size_t)(mb * 128 + row) * DIN + kt * BK + kc * 8);
            float4 f0 = src[0], f1 = src[1];
            __half2 h0 = __floats2half2_rn(f0.x, f0.y);
            __half2 h1 = __floats2half2_rn(f0.z, f0.w);
            __half2 h2 = __floats2half2_rn(f1.x, f1.y);
            __half2 h3 = __floats2half2_rn(f1.z, f1.w);
            uint4 v;
            v.x = *(uint32_t*)&h0; v.y = *(uint32_t*)&h1;
            v.z = *(uint32_t*)&h2; v.w = *(uint32_t*)&h3;
            *(uint4*)(tile + cid * 8) = v;
        }
    } else {
        // ---- fuse W = base + c*sign, transpose to [N][K] ----
        int wb = bx - 8192;
        int nb = wb >> 7, kt = wb & 127;
        float c = __ldg(coeff);
        int n = t & 127, hsel = t >> 7;
        #pragma unroll
        for (int i = 0; i < 8; i++) {
            int kp = hsel * 8 + i;
            size_t off0 = (size_t)(kt * BK + kp * 2) * DOUT + nb * 128 + n;
            size_t off1 = off0 + DOUT;
            float w0 = base[off0] + (mask[off0] ? c : -c);
            float w1 = base[off1] + (mask[off1] ? c : -c);
            __half2 h = __floats2half2_rn(w0, w1);
            sw32[n * 17 + kp] = *(uint32_t*)&h;
        }
        __syncthreads();
        __half* tile = g_B + ((size_t)(nb * NKT + kt) << 12);
        #pragma unroll
        for (int it = 0; it < 2; it++) {
            int cid = it * 256 + t;
            int nn = cid >> 2, kc = cid & 3;
            uint4 v;
            v.x = sw32[nn * 17 + kc * 4 + 0];
            v.y = sw32[nn * 17 + kc * 4 + 1];
            v.z = sw32[nn * 17 + kc * 4 + 2];
            v.w = sw32[nn * 17 + kc * 4 + 3];
            *(uint4*)(tile + cid * 8) = v;
        }
    }
}

// ---------- fp16 GEMM: persistent CTAs, seamless cross-tile cp.async pipeline ----------
__global__ void __launch_bounds__(128, 2) gemm_fp16(float* __restrict__ out) {
    extern __shared__ char smem[];
    const uint32_t sbase = smem_u32(smem);

    const int tid  = threadIdx.x;
    const int lane = tid & 31;
    const int warp = tid >> 5;                // 0..3
    const int wm = (warp & 1) * 64;           // warp tile 64(m) x 64(n)
    const int wn = (warp >> 1) * 64;

    // ldmatrix per-lane base offsets (padded stride-5-chunk layout)
    const int j = lane >> 3, sub = lane & 7;
    uint32_t aoff[4], boff[4];
    #pragma unroll
    for (int mt = 0; mt < 4; mt++) {
        int m = wm + mt * 16 + (j & 1) * 8 + sub;
        aoff[mt] = (uint32_t)((m * 5 + (j >> 1)) << 4);
    }
    #pragma unroll
    for (int np = 0; np < 4; np++) {
        int n = wn + np * 16 + (j >> 1) * 8 + sub;
        boff[np] = (uint32_t)((n * 5 + (j & 1)) << 4) + ASTAGE;
    }

    float acc[4][8][4];

    // --- issue-side state: continuous stream over (tile, kt) for this slot ---
    int it_tile = blockIdx.x;
    int it_kt = 0;
    const __half* iA;
    const __half* iB;
    auto set_issue_bases = [&](int t) {
        int local = t & 255, g = t >> 8;
        int ibm = (g << 3) + (local & 7);
        int ibn = local >> 3;
        iA = g_A + ((size_t)ibm * NKT << 12);
        iB = g_B + ((size_t)ibn * NKT << 12);
    };
    set_issue_bases(it_tile);

    int s_nxt = 0;
    auto adv_issue = [&]() {
        if (it_tile < NTILES) {
            const __half* tA = iA + ((size_t)it_kt << 12);
            const __half* tB = iB + ((size_t)it_kt << 12);
            #pragma unroll
            for (int it = 0; it < 4; it++) {
                int cid = it * 128 + tid;             // 512 chunks each
                uint32_t d = sbase + s_nxt * STAGEB + ((((cid >> 2) * 5) + (cid & 3)) << 4);
                cp16(d, tA + cid * 8);
                cp16(d + ASTAGE, tB + cid * 8);
            }
        }
        asm volatile("cp.async.commit_group;\n");     // empty group keeps cadence at the end
        if (++s_nxt == STAGES) s_nxt = 0;
        if (++it_kt == NKT) {
            it_kt = 0;
            it_tile += GRID;
            if (it_tile < NTILES) set_issue_bases(it_tile);
        }
    };

    auto ldsm_a = [&](const uint32_t st, int ks, uint32_t a[4][4], int mt0, int mt1) {
        #pragma unroll
        for (int mt = mt0; mt < mt1; mt++)
            asm volatile("ldmatrix.sync.aligned.m8n8.x4.shared.b16 {%0,%1,%2,%3}, [%4];"
                         : "=r"(a[mt][0]), "=r"(a[mt][1]), "=r"(a[mt][2]), "=r"(a[mt][3])
                         : "r"(st + aoff[mt] + ks * 32));
    };
    auto ldsm_b = [&](const uint32_t st, int ks, uint32_t b[4][4], int np0, int np1) {
        #pragma unroll
        for (int np = np0; np < np1; np++)
            asm volatile("ldmatrix.sync.aligned.m8n8.x4.shared.b16 {%0,%1,%2,%3}, [%4];"
                         : "=r"(b[np][0]), "=r"(b[np][1]), "=r"(b[np][2]), "=r"(b[np][3])
                         : "r"(st + boff[np] + ks * 32));
    };
    auto mma_half = [&](uint32_t a[4][4], uint32_t b[4][4], int mt0, int mt1) {
        #pragma unroll
        for (int mt = mt0; mt < mt1; mt++)
            #pragma unroll
            for (int np = 0; np < 4; np++)
                #pragma unroll
                for (int h = 0; h < 2; h++) {
                    float* d = acc[mt][np * 2 + h];
                    asm volatile(
                        "mma.sync.aligned.m16n8k16.row.col.f32.f16.f16.f32 "
                        "{%0,%1,%2,%3}, {%4,%5,%6,%7}, {%8,%9}, {%0,%1,%2,%3};\n"
                        : "+f"(d[0]), "+f"(d[1]), "+f"(d[2]), "+f"(d[3])
                        : "r"(a[mt][0]), "r"(a[mt][1]), "r"(a[mt][2]), "r"(a[mt][3]),
                          "r"(b[np][2 * h]), "r"(b[np][2 * h + 1]));
                }
    };

    // prologue: 4 groups in flight (first tile, k-tiles 0..3, stages 0..3)
    adv_issue(); adv_issue(); adv_issue(); adv_issue();
    int s_cur = 0;

    // persistent tile loop — pipeline never drains between tiles
    #pragma unroll 1
    for (int tile = blockIdx.x; tile < NTILES; tile += GRID) {
        #pragma unroll
        for (int a = 0; a < 4; a++)
            #pragma unroll
            for (int b = 0; b < 8; b++)
                #pragma unroll
                for (int d = 0; d < 4; d++) acc[a][b][d] = 0.f;

        #pragma unroll 1
        for (int kt = 0; kt < NKT; kt++) {
            asm volatile("cp.async.wait_group 3;\n");   // pending 4 -> completes s_cur's group
            __syncthreads();

            const uint32_t st = sbase + s_cur * STAGEB;
            uint32_t a0[4][4], b0[4][4], a1[4][4], b1[4][4];

            ldsm_a(st, 0, a0, 0, 4);
            ldsm_b(st, 0, b0, 0, 4);
            adv_issue();                                // next k-tile (possibly next tile / empty)
            mma_half(a0, b0, 0, 1);
            ldsm_a(st, 1, a1, 0, 4);
            mma_half(a0, b0, 1, 2);
            ldsm_b(st, 1, b1, 0, 4);
            mma_half(a0, b0, 2, 4);
            mma_half(a1, b1, 0, 4);

            if (++s_cur == STAGES) s_cur = 0;
        }

        // epilogue for this tile (registers -> gmem; overlaps in-flight loads)
        int local = tile & 255, g = tile >> 8;
        int bm = (g << 3) + (local & 7);
        int bn = local >> 3;
        const int r = lane >> 2, cc = lane & 3;
        #pragma unroll
        for (int mt = 0; mt < 4; mt++) {
            #pragma unroll
            for (int n8 = 0; n8 < 8; n8++) {
                size_t row = (size_t)bm * BM + wm + mt * 16 + r;
                size_t col = (size_t)bn * BN + wn + n8 * 8 + cc * 2;
                float* d = acc[mt][n8];
                *(float2*)(out + row * DOUT + col)       = make_float2(d[0], d[1]);
                *(float2*)(out + (row + 8) * DOUT + col) = make_float2(d[2], d[3]);
            }
        }
    }

    asm volatile("cp.async.wait_group 0;\n");           // settle trailing groups before exit
}

extern "C" void kernel_launch(void* const* d_in, const int* in_sizes, int n_in,
                              void* d_out, int out_size) {
    const float* x     = (const float*)d_in[0];
    const float* base  = (const float*)d_in[1];
    const int*   mask  = (const int*)d_in[2];
    const float* coeff = (const float*)d_in[3];
    float* out = (float*)d_out;

    pack_all<<<12288, 256>>>(x, base, mask, coeff);

    const int smem = STAGES * STAGEB;   // 102400
    cudaFuncSetAttribute(gemm_fp16, cudaFuncAttributeMaxDynamicSharedMemorySize, smem);
    gemm_fp16<<<GRID, 128, smem>>>(out);
}

// round 16
// speedup vs baseline: 1.3002x; 1.3002x over previous
#include <cuda_runtime.h>
#include <cuda_fp16.h>
#include <cstdint>

#define DIN   4096
#define DOUT  4096
#define MTOT  8192
#define BM    128
#define BN    128
#define BK    32
#define NKT   (DIN / BK)      // 128
#define STAGES 5
#define ASTAGE 10240          // 128 rows * 5 chunks * 16B (padded)
#define STAGEB 20480          // A + B per stage

// Packed fp16 operand tiles. Tile (mb,kt) / (nb,kt) = 4096 halves contiguous,
// chunk c (16B, 8 halves) = row (c>>2), kchunk (c&3). A: [M][K]; B: [N][K] (W transposed).
__device__ __half g_A[(size_t)MTOT * DIN];
__device__ __half g_B[(size_t)DOUT * DIN];

__device__ __forceinline__ uint32_t smem_u32(const void* p) {
    uint32_t a;
    asm("{ .reg .u64 t; cvta.to.shared.u64 t, %1; cvt.u32.u64 %0, t; }" : "=r"(a) : "l"(p));
    return a;
}
__device__ __forceinline__ void cp16(uint32_t dst, const void* src) {
    asm volatile("cp.async.cg.shared.global [%0], [%1], 16;\n" :: "r"(dst), "l"(src));
}

// ---------- fused prep: blocks [0,8192) pack x, [8192,12288) fuse+transpose W ----------
__global__ void __launch_bounds__(256) pack_all(const float* __restrict__ x,
                                                const float* __restrict__ base,
                                                const int* __restrict__ mask,
                                                const float* __restrict__ coeff) {
    __shared__ uint32_t sw32[128 * 17];              // used only by W blocks
    int bx = blockIdx.x;
    int t = threadIdx.x;

    if (bx < 8192) {
        // ---- pack x ----
        int mb = bx >> 7, kt = bx & 127;
        __half* tile = g_A + ((size_t)(mb * NKT + kt) << 12);
        #pragma unroll
        for (int it = 0; it < 2; it++) {
            int cid = it * 256 + t;                  // 512 chunks of 8 halves
            int row = cid >> 2, kc = cid & 3;
            const float4* src = (const float4*)(x + (size_t)(mb * 128 + row) * DIN + kt * BK + kc * 8);
            float4 f0 = src[0], f1 = src[1];
            __half2 h0 = __floats2half2_rn(f0.x, f0.y);
            __half2 h1 = __floats2half2_rn(f0.z, f0.w);
            __half2 h2 = __floats2half2_rn(f1.x, f1.y);
            __half2 h3 = __floats2half2_rn(f1.z, f1.w);
            uint4 v;
            v.x = *(uint32_t*)&h0; v.y = *(uint32_t*)&h1;
            v.z = *(uint32_t*)&h2; v.w = *(uint32_t*)&h3;
            *(uint4*)(tile + cid * 8) = v;
        }
    } else {
        // ---- fuse W = base + c*sign, transpose to [N][K] ----
        int wb = bx - 8192;
        int nb = wb >> 7, kt = wb & 127;
        float c = __ldg(coeff);
        int n = t & 127, hsel = t >> 7;
        #pragma unroll
        for (int i = 0; i < 8; i++) {
            int kp = hsel * 8 + i;
            size_t off0 = (size_t)(kt * BK + kp * 2) * DOUT + nb * 128 + n;
            size_t off1 = off0 + DOUT;
            float w0 = base[off0] + (mask[off0] ? c : -c);
            float w1 = base[off1] + (mask[off1] ? c : -c);
            __half2 h = __floats2half2_rn(w0, w1);
            sw32[n * 17 + kp] = *(uint32_t*)&h;
        }
        __syncthreads();
        __half* tile = g_B + ((size_t)(nb * NKT + kt) << 12);
        #pragma unroll
        for (int it = 0; it < 2; it++) {
            int cid = it * 256 + t;
            int nn = cid >> 2, kc = cid & 3;
            uint4 v;
            v.x = sw32[nn * 17 + kc * 4 + 0];
            v.y = sw32[nn * 17 + kc * 4 + 1];
            v.z = sw32[nn * 17 + kc * 4 + 2];
            v.w = sw32[nn * 17 + kc * 4 + 3];
            *(uint4*)(tile + cid * 8) = v;
        }
    }
}

// ---------- fp16 GEMM: 4 warps, 64x64 warp tiles (champion config) ----------
__global__ void __launch_bounds__(128, 2) gemm_fp16(float* __restrict__ out) {
    extern __shared__ char smem[];
    const uint32_t sbase = smem_u32(smem);

    const int tid  = threadIdx.x;
    const int lane = tid & 31;
    const int warp = tid >> 5;                // 0..3
    const int wm = (warp & 1) * 64;           // warp tile 64(m) x 64(n)
    const int wn = (warp >> 1) * 64;

    // L2 block swizzle: 8 m-blocks share one n-block column
    int pid = blockIdx.x;
    int local = pid & 255, g = pid >> 8;
    int bm = (g << 3) + (local & 7);
    int bn = local >> 3;

    const __half* tA0 = g_A + ((size_t)bm * NKT << 12);
    const __half* tB0 = g_B + ((size_t)bn * NKT << 12);

    // ldmatrix per-lane base offsets (padded stride-5-chunk layout)
    const int j = lane >> 3, sub = lane & 7;
    uint32_t aoff[4], boff[4];
    #pragma unroll
    for (int mt = 0; mt < 4; mt++) {
        int m = wm + mt * 16 + (j & 1) * 8 + sub;
        aoff[mt] = (uint32_t)((m * 5 + (j >> 1)) << 4);
    }
    #pragma unroll
    for (int np = 0; np < 4; np++) {
        int n = wn + np * 16 + (j >> 1) * 8 + sub;
        boff[np] = (uint32_t)((n * 5 + (j & 1)) << 4) + ASTAGE;
    }

    float acc[4][8][4];
    #pragma unroll
    for (int a = 0; a < 4; a++)
        #pragma unroll
        for (int b = 0; b < 8; b++)
            #pragma unroll
            for (int d = 0; d < 4; d++) acc[a][b][d] = 0.f;

    auto issue = [&](int kt, int stage) {
        const __half* tA = tA0 + ((size_t)kt << 12);
        const __half* tB = tB0 + ((size_t)kt << 12);
        #pragma unroll
        for (int it = 0; it < 4; it++) {
            int cid = it * 128 + tid;             // 512 chunks each
            uint32_t d = sbase + stage * STAGEB + ((((cid >> 2) * 5) + (cid & 3)) << 4);
            cp16(d, tA + cid * 8);
            cp16(d + ASTAGE, tB + cid * 8);
        }
        asm volatile("cp.async.commit_group;\n");
    };

    auto ldsm_a = [&](const uint32_t st, int ks, uint32_t a[4][4], int mt0, int mt1) {
        #pragma unroll
        for (int mt = mt0; mt < mt1; mt++)
            asm volatile("ldmatrix.sync.aligned.m8n8.x4.shared.b16 {%0,%1,%2,%3}, [%4];"
                         : "=r"(a[mt][0]), "=r"(a[mt][1]), "=r"(a[mt][2]), "=r"(a[mt][3])
                         : "r"(st + aoff[mt] + ks * 32));
    };
    auto ldsm_b = [&](const uint32_t st, int ks, uint32_t b[4][4], int np0, int np1) {
        #pragma unroll
        for (int np = np0; np < np1; np++)
            asm volatile("ldmatrix.sync.aligned.m8n8.x4.shared.b16 {%0,%1,%2,%3}, [%4];"
                         : "=r"(b[np][0]), "=r"(b[np][1]), "=r"(b[np][2]), "=r"(b[np][3])
                         : "r"(st + boff[np] + ks * 32));
    };

    auto mma_half = [&](uint32_t a[4][4], uint32_t b[4][4], int mt0, int mt1) {
        #pragma unroll
        for (int mt = mt0; mt < mt1; mt++)
            #pragma unroll
            for (int np = 0; np < 4; np++)
                #pragma unroll
                for (int h = 0; h < 2; h++) {
                    float* d = acc[mt][np * 2 + h];
                    asm volatile(
                        "mma.sync.aligned.m16n8k16.row.col.f32.f16.f16.f32 "
                        "{%0,%1,%2,%3}, {%4,%5,%6,%7}, {%8,%9}, {%0,%1,%2,%3};\n"
                        : "+f"(d[0]), "+f"(d[1]), "+f"(d[2]), "+f"(d[3])
                        : "r"(a[mt][0]), "r"(a[mt][1]), "r"(a[mt][2]), "r"(a[mt][3]),
                          "r"(b[np][2 * h]), "r"(b[np][2 * h + 1]));
                }
    };

    // prologue: stages 0..3 in flight (4-deep lookahead)
    issue(0, 0); issue(1, 1); issue(2, 2); issue(3, 3);

    // mainloop: wait + barrier at TOP (proven), fine-grain LDSM interleave.
    int s_cur = 0, s_nxt = 4;
    #pragma unroll 1
    for (int kt = 0; kt < NKT; kt++) {
        if (kt + 3 < NKT) asm volatile("cp.async.wait_group 3;\n");
        else              asm volatile("cp.async.wait_group 0;\n");
        __syncthreads();

        const uint32_t st = sbase + s_cur * STAGEB;
        uint32_t a0[4][4], b0[4][4], a1[4][4], b1[4][4];

        ldsm_a(st, 0, a0, 0, 4);                 // ks0 A (critical path)
        ldsm_b(st, 0, b0, 0, 4);                 // ks0 B
        if (kt + 4 < NKT) issue(kt + 4, s_nxt);  // LSU work under LDSM latency
        mma_half(a0, b0, 0, 1);                  // 8 MMAs
        ldsm_a(st, 1, a1, 0, 4);                 // 4 LDSM under MMAs
        mma_half(a0, b0, 1, 2);                  // 8 MMAs
        ldsm_b(st, 1, b1, 0, 4);                 // 4 LDSM under MMAs
        mma_half(a0, b0, 2, 4);                  // 16 MMAs
        mma_half(a1, b1, 0, 4);                  // 32 MMAs

        if (++s_cur == STAGES) s_cur = 0;
        if (++s_nxt == STAGES) s_nxt = 0;
    }

    // epilogue: streaming stores (evict-first) — out is write-once, keep L2
    // for operand tiles of still-running CTAs.
    const int r = lane >> 2, cc = lane & 3;
    #pragma unroll
    for (int mt = 0; mt < 4; mt++) {
        #pragma unroll
        for (int n8 = 0; n8 < 8; n8++) {
            size_t row = (size_t)bm * BM + wm + mt * 16 + r;
            size_t col = (size_t)bn * BN + wn + n8 * 8 + cc * 2;
            float* d = acc[mt][n8];
            __stcs((float2*)(out + row * DOUT + col),       make_float2(d[0], d[1]));
            __stcs((float2*)(out + (row + 8) * DOUT + col), make_float2(d[2], d[3]));
        }
    }
}

extern "C" void kernel_launch(void* const* d_in, const int* in_sizes, int n_in,
                              void* d_out, int out_size) {
    const float* x     = (const float*)d_in[0];
    const float* base  = (const float*)d_in[1];
    const int*   mask  = (const int*)d_in[2];
    const float* coeff = (const float*)d_in[3];
    float* out = (float*)d_out;

    pack_all<<<12288, 256>>>(x, base, mask, coeff);

    const int smem = STAGES * STAGEB;   // 102400
    cudaFuncSetAttribute(gemm_fp16, cudaFuncAttributeMaxDynamicSharedMemorySize, smem);
    gemm_fp16<<<(MTOT / BM) * (DOUT / BN), 128, smem>>>(out);
}

// round 17
// speedup vs baseline: 1.3068x; 1.0051x over previous
#include <cuda_runtime.h>
#include <cuda_fp16.h>
#include <cstdint>

#define DIN   4096
#define DOUT  4096
#define MTOT  8192
#define BM    128
#define BN    128
#define BK    32
#define NKT   (DIN / BK)      // 128
#define STAGES 5
#define STAGEB 10240          // B stage: 128 rows * 5 chunks * 16B (padded)

// g_A: fragment-packed fp16 A tiles. Tile (mb,kt) = 8192B laid out as
//   [q4 0..7][p 0..63][16B], q4 = ks*4+mt (fragment uint4), p = h*32+lane.
// g_B: [N][K] fp16 tiles (W fused+transposed), chunk layout as before.
__device__ __half g_A[(size_t)MTOT * DIN];
__device__ __half g_B[(size_t)DOUT * DIN];

__device__ __forceinline__ uint32_t smem_u32(const void* p) {
    uint32_t a;
    asm("{ .reg .u64 t; cvta.to.shared.u64 t, %1; cvt.u32.u64 %0, t; }" : "=r"(a) : "l"(p));
    return a;
}
__device__ __forceinline__ void cp16(uint32_t dst, const void* src) {
    asm volatile("cp.async.cg.shared.global [%0], [%1], 16;\n" :: "r"(dst), "l"(src));
}

// ---------- fused prep: blocks [0,8192) pack x (fragment order), [8192,12288) fuse W ----------
__global__ void __launch_bounds__(256) pack_all(const float* __restrict__ x,
                                                const float* __restrict__ base,
                                                const int* __restrict__ mask,
                                                const float* __restrict__ coeff) {
    __shared__ uint32_t s32[128 * 17];               // staging (both paths)
    int bx = blockIdx.x;
    int t = threadIdx.x;

    if (bx < 8192) {
        // ---- pack x into mma-fragment order ----
        int mb = bx >> 7, kt = bx & 127;
        // stage: s32[row][kp] = half2(x[row][2kp], x[row][2kp+1]), row 0..127, kp 0..15
        #pragma unroll
        for (int i = 0; i < 8; i++) {
            int idx = i * 256 + t;
            int row = idx >> 4, kp = idx & 15;
            const float2 v = *(const float2*)(x + (size_t)(mb * 128 + row) * DIN + kt * BK + kp * 2);
            __half2 h = __floats2half2_rn(v.x, v.y);
            s32[row * 17 + kp] = *(uint32_t*)&h;
        }
        __syncthreads();
        // gather: p = t&63 -> (h,lane); part = t>>6 -> two q4 fragments
        int p = t & 63, part = t >> 6;
        int h = p >> 5, lane = p & 31;
        int g = lane >> 2, tt = lane & 3;
        uint4* tileo = (uint4*)g_A + (size_t)(mb * NKT + kt) * 512;
        #pragma unroll
        for (int jj = 0; jj < 2; jj++) {
            int q4 = part * 2 + jj;                  // 0..7
            int ks = q4 >> 2, mt = q4 & 3;
            int row0 = h * 64 + mt * 16 + g;
            uint4 w;
            // rr: row += (rr&1)*8 ; kp = ks*8 + tt + (rr&2)*2
            w.x = s32[(row0    ) * 17 + ks * 8 + tt    ];
            w.y = s32[(row0 + 8) * 17 + ks * 8 + tt    ];
            w.z = s32[(row0    ) * 17 + ks * 8 + tt + 4];
            w.w = s32[(row0 + 8) * 17 + ks * 8 + tt + 4];
            tileo[q4 * 64 + p] = w;
        }
    } else {
        // ---- fuse W = base + c*sign, transpose to [N][K] ----
        int wb = bx - 8192;
        int nb = wb >> 7, kt = wb & 127;
        float c = __ldg(coeff);
        int n = t & 127, hsel = t >> 7;
        #pragma unroll
        for (int i = 0; i < 8; i++) {
            int kp = hsel * 8 + i;
            size_t off0 = (size_t)(kt * BK + kp * 2) * DOUT + nb * 128 + n;
            size_t off1 = off0 + DOUT;
            float w0 = base[off0] + (mask[off0] ? c : -c);
            float w1 = base[off1] + (mask[off1] ? c : -c);
            __half2 h = __floats2half2_rn(w0, w1);
            s32[n * 17 + kp] = *(uint32_t*)&h;
        }
        __syncthreads();
        __half* tile = g_B + ((size_t)(nb * NKT + kt) << 12);
        #pragma unroll
        for (int it = 0; it < 2; it++) {
            int cid = it * 256 + t;
            int nn = cid >> 2, kc = cid & 3;
            uint4 v;
            v.x = s32[nn * 17 + kc * 4 + 0];
            v.y = s32[nn * 17 + kc * 4 + 1];
            v.z = s32[nn * 17 + kc * 4 + 2];
            v.w = s32[nn * 17 + kc * 4 + 3];
            *(uint4*)(tile + cid * 8) = v;
        }
    }
}

// ---------- fp16 GEMM: A direct from L2 (fragment LDG), B via smem/ldsm ----------
__global__ void __launch_bounds__(128, 2) gemm_fp16(float* __restrict__ out) {
    extern __shared__ char smem[];
    const uint32_t sbase = smem_u32(smem);

    const int tid  = threadIdx.x;
    const int lane = tid & 31;
    const int warp = tid >> 5;                // 0..3
    const int wm = (warp & 1) * 64;           // warp tile 64(m) x 64(n)
    const int wn = (warp >> 1) * 64;

    // L2 block swizzle: 8 m-blocks share one n-block column
    int pid = blockIdx.x;
    int local = pid & 255, g = pid >> 8;
    int bm = (g << 3) + (local & 7);
    int bn = local >> 3;

    // A: per-thread fragment stream
    const uint4* pA = (const uint4*)g_A + (size_t)(bm * NKT) * 512 + ((warp & 1) * 32 + lane);
    const __half* tB0 = g_B + ((size_t)bn * NKT << 12);

    // ldmatrix per-lane base offsets for B (padded stride-5-chunk layout)
    const int j = lane >> 3, sub = lane & 7;
    uint32_t boff[4];
    #pragma unroll
    for (int np = 0; np < 4; np++) {
        int n = wn + np * 16 + (j >> 1) * 8 + sub;
        boff[np] = (uint32_t)((n * 5 + (j & 1)) << 4);
    }

    float acc[4][8][4];
    #pragma unroll
    for (int a = 0; a < 4; a++)
        #pragma unroll
        for (int b = 0; b < 8; b++)
            #pragma unroll
            for (int d = 0; d < 4; d++) acc[a][b][d] = 0.f;

    auto issueB = [&](int kt, int stage) {
        const __half* tB = tB0 + ((size_t)kt << 12);
        #pragma unroll
        for (int it = 0; it < 4; it++) {
            int cid = it * 128 + tid;             // 512 chunks
            uint32_t d = sbase + stage * STAGEB + ((((cid >> 2) * 5) + (cid & 3)) << 4);
            cp16(d, tB + cid * 8);
        }
        asm volatile("cp.async.commit_group;\n");
    };

    auto ldsm_b = [&](const uint32_t st, int ks, uint32_t b[4][4]) {
        #pragma unroll
        for (int np = 0; np < 4; np++)
            asm volatile("ldmatrix.sync.aligned.m8n8.x4.shared.b16 {%0,%1,%2,%3}, [%4];"
                         : "=r"(b[np][0]), "=r"(b[np][1]), "=r"(b[np][2]), "=r"(b[np][3])
                         : "r"(st + boff[np] + ks * 32));
    };

    // one mt-row of MMAs (8) using fragment uint4 av
    auto mma_mt = [&](const uint4& av, uint32_t b[4][4], int mt) {
        #pragma unroll
        for (int np = 0; np < 4; np++)
            #pragma unroll
            for (int h = 0; h < 2; h++) {
                float* d = acc[mt][np * 2 + h];
                asm volatile(
                    "mma.sync.aligned.m16n8k16.row.col.f32.f16.f16.f32 "
                    "{%0,%1,%2,%3}, {%4,%5,%6,%7}, {%8,%9}, {%0,%1,%2,%3};\n"
                    : "+f"(d[0]), "+f"(d[1]), "+f"(d[2]), "+f"(d[3])
                    : "r"(av.x), "r"(av.y), "r"(av.z), "r"(av.w),
                      "r"(b[np][2 * h]), "r"(b[np][2 * h + 1]));
            }
    };

    uint4 A0[8], A1[8];
    auto ldgA = [&](uint4* buf, int i0, int i1, int kt) {
        const uint4* src = pA + (size_t)kt * 512;
        #pragma unroll
        for (int i = i0; i < i1; i++)
            buf[i] = __ldg(src + i * 64);
    };

    // prologue: B stages 0..3 in flight; A frags for k-tiles 0 and 1 in regs
    issueB(0, 0); issueB(1, 1); issueB(2, 2); issueB(3, 3);
    ldgA(A0, 0, 8, 0);
    ldgA(A1, 0, 8, 1);

    int s_cur = 0, s_nxt = 4;
    #pragma unroll 1
    for (int kt = 0; kt < NKT; kt += 2) {
        // ---- half A: k-tile kt, fragments in A0 ----
        {
            if (kt + 3 < NKT) asm volatile("cp.async.wait_group 3;\n");
            else              asm volatile("cp.async.wait_group 0;\n");
            __syncthreads();
            const uint32_t st = sbase + s_cur * STAGEB;
            uint32_t b0[4][4], b1[4][4];
            ldsm_b(st, 0, b0);
            if (kt + 4 < NKT) issueB(kt + 4, s_nxt);
            mma_mt(A0[0], b0, 0); mma_mt(A0[1], b0, 1);
            ldsm_b(st, 1, b1);
            mma_mt(A0[2], b0, 2); mma_mt(A0[3], b0, 3);
            int kp = (kt + 2 < NKT) ? kt + 2 : NKT - 1;
            ldgA(A0, 0, 4, kp);                      // reload ks0 frags for kt+2
            mma_mt(A0[4], b1, 0); mma_mt(A0[5], b1, 1);
            mma_mt(A0[6], b1, 2); mma_mt(A0[7], b1, 3);
            ldgA(A0, 4, 8, kp);                      // reload ks1 frags for kt+2
            if (++s_cur == STAGES) s_cur = 0;
            if (++s_nxt == STAGES) s_nxt = 0;
        }
        // ---- half B: k-tile kt+1, fragments in A1 ----
        {
            if (kt + 4 < NKT) asm volatile("cp.async.wait_group 3;\n");
            else              asm volatile("cp.async.wait_group 0;\n");
            __syncthreads();
            const uint32_t st = sbase + s_cur * STAGEB;
            uint32_t b0[4][4], b1[4][4];
            ldsm_b(st, 0, b0);
            if (kt + 5 < NKT) issueB(kt + 5, s_nxt);
            mma_mt(A1[0], b0, 0); mma_mt(A1[1], b0, 1);
            ldsm_b(st, 1, b1);
            mma_mt(A1[2], b0, 2); mma_mt(A1[3], b0, 3);
            int kp = (kt + 3 < NKT) ? kt + 3 : NKT - 1;
            ldgA(A1, 0, 4, kp);                      // reload ks0 frags for kt+3
            mma_mt(A1[4], b1, 0); mma_mt(A1[5], b1, 1);
            mma_mt(A1[6], b1, 2); mma_mt(A1[7], b1, 3);
            ldgA(A1, 4, 8, kp);                      // reload ks1 frags for kt+3
            if (++s_cur == STAGES) s_cur = 0;
            if (++s_nxt == STAGES) s_nxt = 0;
        }
    }

    // epilogue: streaming stores (evict-first)
    const int r = lane >> 2, cc = lane & 3;
    #pragma unroll
    for (int mt = 0; mt < 4; mt++) {
        #pragma unroll
        for (int n8 = 0; n8 < 8; n8++) {
            size_t row = (size_t)bm * BM + wm + mt * 16 + r;
            size_t col = (size_t)bn * BN + wn + n8 * 8 + cc * 2;
            float* d = acc[mt][n8];
            __stcs((float2*)(out + row * DOUT + col),       make_float2(d[0], d[1]));
            __stcs((float2*)(out + (row + 8) * DOUT + col), make_float2(d[2], d[3]));
        }
    }
}

extern "C" void kernel_launch(void* const* d_in, const int* in_sizes, int n_in,
                              void* d_out, int out_size) {
    const float* x     = (const float*)d_in[0];
    const float* base  = (const float*)d_in[1];
    const int*   mask  = (const int*)d_in[2];
    const float* coeff = (const float*)d_in[3];
    float* out = (float*)d_out;

    pack_all<<<12288, 256>>>(x, base, mask, coeff);

    const int smem = STAGES * STAGEB;   // 51200
    cudaFuncSetAttribute(gemm_fp16, cudaFuncAttributeMaxDynamicSharedMemorySize, smem);
    gemm_fp16<<<(MTOT / BM) * (DOUT / BN), 128, smem>>>(out);
}